// round 4
// baseline (speedup 1.0000x reference)
#include <cuda_runtime.h>
#include <cuda_bf16.h>
#include <math.h>

#define N_NODES 100000
#define E_EDGES 3200000
#define F_IN    256
#define F_HID   16
#define F_OUT   40

// -------- scratch (static device globals; 16B-aligned for float4 access) ----
__device__ __align__(16) float g_deg [N_NODES];
__device__ __align__(16) float g_dinv[N_NODES];
__device__ __align__(16) float g_h1  [N_NODES * F_HID];
__device__ __align__(16) float g_agg1[N_NODES * F_HID];
__device__ __align__(16) float g_r1  [N_NODES * F_HID];
__device__ __align__(16) float g_agg2[N_NODES * F_HID];
__device__ int g_idx32;   // 1 => edge_index stored as int32, 0 => int64

// index loader: position p in the flattened [2*E] edge_index array
__device__ __forceinline__ int load_idx(const void* __restrict__ ei, long long p) {
    if (g_idx32) return ((const int*)ei)[p];
    return (int)(((const long long*)ei)[p]);
}

// ---------------------------------------------------------------------------
// 0. detect edge_index dtype: int64 values from randint(0,100000) are always
//    in range; int32 pairs misread as int64 produce huge values.
// ---------------------------------------------------------------------------
__global__ void k_detect(const long long* __restrict__ ei) {
    if (threadIdx.x == 0 && blockIdx.x == 0) {
        int is32 = 0;
        for (int i = 0; i < 4096; i++) {
            long long v = ei[i];
            if (v < 0 || v >= N_NODES) { is32 = 1; break; }
        }
        g_idx32 = is32;
    }
}

// ---------------------------------------------------------------------------
// 1. degree: deg[i] = 1 (self loop) + sum_{e: col==i} w[e]
// ---------------------------------------------------------------------------
__global__ void k_deg_init() {
    int i = blockIdx.x * blockDim.x + threadIdx.x;
    if (i < N_NODES) g_deg[i] = 1.0f;
}

__global__ void k_deg_edge(const void* __restrict__ ei,
                           const float* __restrict__ ew) {
    int e = blockIdx.x * blockDim.x + threadIdx.x;
    if (e < E_EDGES) {
        int col = load_idx(ei, (long long)E_EDGES + e);
        if ((unsigned)col < (unsigned)N_NODES)
            atomicAdd(&g_deg[col], ew[e]);
    }
}

__global__ void k_dinv() {
    int i = blockIdx.x * blockDim.x + threadIdx.x;
    if (i < N_NODES) {
        float d = g_deg[i];
        g_dinv[i] = (d > 0.0f) ? rsqrtf(d) : 0.0f;
    }
}

// ---------------------------------------------------------------------------
// 2. h1 = x @ W1   (N x 256) @ (256 x 16), thread-per-node, W1 in smem
//    fused with self-loop init: agg1 = h1 * dinv^2
// ---------------------------------------------------------------------------
__global__ void k_gemm1(const float* __restrict__ x,
                        const float* __restrict__ W1) {
    __shared__ float sW[F_IN * F_HID];   // 16 KB
    for (int i = threadIdx.x; i < F_IN * F_HID; i += blockDim.x)
        sW[i] = W1[i];
    __syncthreads();

    int node = blockIdx.x * blockDim.x + threadIdx.x;
    if (node >= N_NODES) return;

    float acc[F_HID];
#pragma unroll
    for (int f = 0; f < F_HID; f++) acc[f] = 0.0f;

    const float4* xr = reinterpret_cast<const float4*>(x + (size_t)node * F_IN);
#pragma unroll 4
    for (int k4 = 0; k4 < F_IN / 4; k4++) {
        float4 xv = xr[k4];
        int kb = k4 * 4;
#pragma unroll
        for (int f = 0; f < F_HID; f++) {
            acc[f] = fmaf(xv.x, sW[(kb + 0) * F_HID + f], acc[f]);
            acc[f] = fmaf(xv.y, sW[(kb + 1) * F_HID + f], acc[f]);
            acc[f] = fmaf(xv.z, sW[(kb + 2) * F_HID + f], acc[f]);
            acc[f] = fmaf(xv.w, sW[(kb + 3) * F_HID + f], acc[f]);
        }
    }

    float di = g_dinv[node];
    float dii = di * di;
    float4* h1o  = reinterpret_cast<float4*>(g_h1   + (size_t)node * F_HID);
    float4* a1o  = reinterpret_cast<float4*>(g_agg1 + (size_t)node * F_HID);
#pragma unroll
    for (int q = 0; q < F_HID / 4; q++) {
        h1o[q] = make_float4(acc[q*4+0], acc[q*4+1], acc[q*4+2], acc[q*4+3]);
        a1o[q] = make_float4(acc[q*4+0]*dii, acc[q*4+1]*dii,
                             acc[q*4+2]*dii, acc[q*4+3]*dii);
    }
}

// ---------------------------------------------------------------------------
// 3. edge scatter: dst[col,f] += src[row,f] * dinv[row]*w*dinv[col]
//    thread-per-(edge, feature); layer selects src/dst globals
// ---------------------------------------------------------------------------
__global__ void k_scatter(const void* __restrict__ ei,
                          const float* __restrict__ ew,
                          int layer) {
    unsigned int gid = blockIdx.x * blockDim.x + threadIdx.x;
    if (gid >= (unsigned int)E_EDGES * F_HID) return;
    int e = (int)(gid >> 4);
    int f = (int)(gid & 15);

    int row = load_idx(ei, e);
    int col = load_idx(ei, (long long)E_EDGES + e);
    if ((unsigned)row >= (unsigned)N_NODES) return;
    if ((unsigned)col >= (unsigned)N_NODES) return;
    float norm = g_dinv[row] * ew[e] * g_dinv[col];

    const float* src = (layer == 0) ? g_h1 : g_r1;
    float*       dst = (layer == 0) ? g_agg1 : g_agg2;

    atomicAdd(&dst[(size_t)col * F_HID + f],
              src[(size_t)row * F_HID + f] * norm);
}

// ---------------------------------------------------------------------------
// 4. r1 = relu(agg1 + b1); agg2 self-loop init = r1 * dinv^2
// ---------------------------------------------------------------------------
__global__ void k_relu_init2(const float* __restrict__ b1) {
    int i = blockIdx.x * blockDim.x + threadIdx.x;
    if (i >= N_NODES * F_HID) return;
    int node = i >> 4;
    int f = i & 15;
    float v = fmaxf(g_agg1[i] + b1[f], 0.0f);
    g_r1[i] = v;
    float di = g_dinv[node];
    g_agg2[i] = v * (di * di);
}

// ---------------------------------------------------------------------------
// 5. out = log_softmax(agg2 @ W2 + b2), thread-per-node, W2/b2 in smem
// ---------------------------------------------------------------------------
__global__ void k_final(const float* __restrict__ W2,
                        const float* __restrict__ b2,
                        float* __restrict__ out) {
    __shared__ float sW[F_HID * F_OUT];   // 2.56 KB
    __shared__ float sb[F_OUT];
    for (int i = threadIdx.x; i < F_HID * F_OUT; i += blockDim.x) sW[i] = W2[i];
    for (int i = threadIdx.x; i < F_OUT; i += blockDim.x) sb[i] = b2[i];
    __syncthreads();

    int node = blockIdx.x * blockDim.x + threadIdx.x;
    if (node >= N_NODES) return;

    float a[F_HID];
    const float4* ar = reinterpret_cast<const float4*>(g_agg2 + (size_t)node * F_HID);
#pragma unroll
    for (int q = 0; q < F_HID / 4; q++) {
        float4 v = ar[q];
        a[q*4+0] = v.x; a[q*4+1] = v.y; a[q*4+2] = v.z; a[q*4+3] = v.w;
    }

    float z[F_OUT];
#pragma unroll
    for (int c = 0; c < F_OUT; c++) {
        float s = sb[c];
#pragma unroll
        for (int k = 0; k < F_HID; k++)
            s = fmaf(a[k], sW[k * F_OUT + c], s);
        z[c] = s;
    }

    float m = z[0];
#pragma unroll
    for (int c = 1; c < F_OUT; c++) m = fmaxf(m, z[c]);
    float s = 0.0f;
#pragma unroll
    for (int c = 0; c < F_OUT; c++) s += expf(z[c] - m);
    float lse = m + logf(s);

    float* o = out + (size_t)node * F_OUT;
#pragma unroll
    for (int c = 0; c < F_OUT; c++) o[c] = z[c] - lse;
}

// ---------------------------------------------------------------------------
// launch — bind inputs by element count (robust to metadata ordering)
// ---------------------------------------------------------------------------
extern "C" void kernel_launch(void* const* d_in, const int* in_sizes, int n_in,
                              void* d_out, int out_size) {
    const float* x  = nullptr;
    const void*  ei = nullptr;
    const float* ew = nullptr;
    const float* W1 = nullptr;
    const float* b1 = nullptr;
    const float* W2 = nullptr;
    const float* b2 = nullptr;

    for (int i = 0; i < n_in; i++) {
        switch (in_sizes[i]) {
            case N_NODES * F_IN:   x  = (const float*)d_in[i]; break; // 25,600,000
            case 2 * E_EDGES:      ei = d_in[i];               break; //  6,400,000
            case E_EDGES:          ew = (const float*)d_in[i]; break; //  3,200,000
            case F_IN * F_HID:     W1 = (const float*)d_in[i]; break; //      4,096
            case F_HID:            b1 = (const float*)d_in[i]; break; //         16
            case F_HID * F_OUT:    W2 = (const float*)d_in[i]; break; //        640
            case F_OUT:            b2 = (const float*)d_in[i]; break; //         40
            default: break;
        }
    }
    float* out = (float*)d_out;

    const int T = 256;

    // dtype detection for edge_index
    k_detect<<<1, 32>>>((const long long*)ei);

    // degree + dinv
    k_deg_init<<<(N_NODES + T - 1) / T, T>>>();
    k_deg_edge<<<(E_EDGES + T - 1) / T, T>>>(ei, ew);
    k_dinv<<<(N_NODES + T - 1) / T, T>>>();

    // layer 1 (gemm fused with self-loop init)
    k_gemm1<<<(N_NODES + 127) / 128, 128>>>(x, W1);
    {
        unsigned int total = (unsigned int)E_EDGES * F_HID;
        k_scatter<<<(total + T - 1) / T, T>>>(ei, ew, 0);
    }

    // relu + layer 2 aggregation
    k_relu_init2<<<(N_NODES * F_HID + T - 1) / T, T>>>(b1);
    {
        unsigned int total = (unsigned int)E_EDGES * F_HID;
        k_scatter<<<(total + T - 1) / T, T>>>(ei, ew, 1);
    }

    // out-projection + log_softmax
    k_final<<<(N_NODES + 127) / 128, 128>>>(W2, b2, out);
}

// round 5
// speedup vs baseline: 1.4433x; 1.4433x over previous
#include <cuda_runtime.h>
#include <cuda_bf16.h>
#include <math.h>

#define N_NODES 100000
#define E_EDGES 3200000
#define F_IN    256
#define F_HID   16
#define F_OUT   40

// -------- scratch (static device globals; 16B-aligned) -----------------------
__device__ __align__(16) float g_deg [N_NODES];
__device__ __align__(16) float g_dinv[N_NODES];
__device__ __align__(16) float g_h1  [N_NODES * F_HID];
__device__ __align__(16) float g_agg1[N_NODES * F_HID];
__device__ __align__(16) float g_r1  [N_NODES * F_HID];
__device__ __align__(16) float g_agg2[N_NODES * F_HID];
__device__ __align__(16) int   g_row [E_EDGES];
__device__ __align__(16) int   g_col [E_EDGES];
__device__ __align__(16) float g_norm[E_EDGES];
__device__ int g_idx32;   // 1 => edge_index stored as int32, 0 => int64

__device__ __forceinline__ int load_idx(const void* __restrict__ ei, long long p) {
    if (g_idx32) return ((const int*)ei)[p];
    return (int)(((const long long*)ei)[p]);
}

// ---------------------------------------------------------------------------
// 0. detect edge_index dtype
// ---------------------------------------------------------------------------
__global__ void k_detect(const long long* __restrict__ ei) {
    if (threadIdx.x == 0 && blockIdx.x == 0) {
        int is32 = 0;
        for (int i = 0; i < 4096; i++) {
            long long v = ei[i];
            if (v < 0 || v >= N_NODES) { is32 = 1; break; }
        }
        g_idx32 = is32;
    }
}

// ---------------------------------------------------------------------------
// 1. degree init + edge pass: decode indices to int32 once, accumulate degree
// ---------------------------------------------------------------------------
__global__ void k_deg_init() {
    int i = blockIdx.x * blockDim.x + threadIdx.x;
    if (i < N_NODES) g_deg[i] = 1.0f;
}

__global__ void k_edges(const void* __restrict__ ei,
                        const float* __restrict__ ew) {
    int e = blockIdx.x * blockDim.x + threadIdx.x;
    if (e >= E_EDGES) return;
    int row = load_idx(ei, e);
    int col = load_idx(ei, (long long)E_EDGES + e);
    if ((unsigned)row >= (unsigned)N_NODES) row = 0;
    if ((unsigned)col >= (unsigned)N_NODES) col = 0;
    g_row[e] = row;
    g_col[e] = col;
    atomicAdd(&g_deg[col], ew[e]);
}

__global__ void k_dinv() {
    int i = blockIdx.x * blockDim.x + threadIdx.x;
    if (i < N_NODES) {
        float d = g_deg[i];
        g_dinv[i] = (d > 0.0f) ? rsqrtf(d) : 0.0f;
    }
}

// per-edge norm = dinv[row] * w * dinv[col]
__global__ void k_prep() {
    int e = blockIdx.x * blockDim.x + threadIdx.x;
    if (e >= E_EDGES) return;
    g_norm[e] = g_dinv[g_row[e]] * g_norm[e] * g_dinv[g_col[e]];
}

// stash raw w into g_norm so k_prep can run in-place
__global__ void k_copy_w(const float* __restrict__ ew) {
    int e = blockIdx.x * blockDim.x + threadIdx.x;
    if (e < E_EDGES) g_norm[e] = ew[e];
}

// ---------------------------------------------------------------------------
// 2. h1 = x @ W1, fused with self-loop init agg1 = h1 * dinv^2
// ---------------------------------------------------------------------------
__global__ void k_gemm1(const float* __restrict__ x,
                        const float* __restrict__ W1) {
    __shared__ float sW[F_IN * F_HID];   // 16 KB
    for (int i = threadIdx.x; i < F_IN * F_HID; i += blockDim.x)
        sW[i] = W1[i];
    __syncthreads();

    int node = blockIdx.x * blockDim.x + threadIdx.x;
    if (node >= N_NODES) return;

    float acc[F_HID];
#pragma unroll
    for (int f = 0; f < F_HID; f++) acc[f] = 0.0f;

    const float4* xr = reinterpret_cast<const float4*>(x + (size_t)node * F_IN);
#pragma unroll 4
    for (int k4 = 0; k4 < F_IN / 4; k4++) {
        float4 xv = xr[k4];
        int kb = k4 * 4;
#pragma unroll
        for (int f = 0; f < F_HID; f++) {
            acc[f] = fmaf(xv.x, sW[(kb + 0) * F_HID + f], acc[f]);
            acc[f] = fmaf(xv.y, sW[(kb + 1) * F_HID + f], acc[f]);
            acc[f] = fmaf(xv.z, sW[(kb + 2) * F_HID + f], acc[f]);
            acc[f] = fmaf(xv.w, sW[(kb + 3) * F_HID + f], acc[f]);
        }
    }

    float di = g_dinv[node];
    float dii = di * di;
    float4* h1o = reinterpret_cast<float4*>(g_h1   + (size_t)node * F_HID);
    float4* a1o = reinterpret_cast<float4*>(g_agg1 + (size_t)node * F_HID);
#pragma unroll
    for (int q = 0; q < F_HID / 4; q++) {
        h1o[q] = make_float4(acc[q*4+0], acc[q*4+1], acc[q*4+2], acc[q*4+3]);
        a1o[q] = make_float4(acc[q*4+0]*dii, acc[q*4+1]*dii,
                             acc[q*4+2]*dii, acc[q*4+3]*dii);
    }
}

// ---------------------------------------------------------------------------
// 3. edge scatter, one thread per edge: 4x LDG.128 gather + 4x red.v4
// ---------------------------------------------------------------------------
__device__ __forceinline__ void red_v4(float* p, float4 v) {
    asm volatile("red.global.add.v4.f32 [%0], {%1, %2, %3, %4};"
                 :: "l"(p), "f"(v.x), "f"(v.y), "f"(v.z), "f"(v.w)
                 : "memory");
}

template <int LAYER>
__global__ void k_scatter() {
    int e = blockIdx.x * blockDim.x + threadIdx.x;
    if (e >= E_EDGES) return;

    int row = g_row[e];
    int col = g_col[e];
    float norm = g_norm[e];

    const float4* src = reinterpret_cast<const float4*>(
        (LAYER == 0 ? g_h1 : g_r1) + (size_t)row * F_HID);
    float* dst = (LAYER == 0 ? g_agg1 : g_agg2) + (size_t)col * F_HID;

    float4 v0 = src[0], v1 = src[1], v2 = src[2], v3 = src[3];
    red_v4(dst + 0,  make_float4(v0.x*norm, v0.y*norm, v0.z*norm, v0.w*norm));
    red_v4(dst + 4,  make_float4(v1.x*norm, v1.y*norm, v1.z*norm, v1.w*norm));
    red_v4(dst + 8,  make_float4(v2.x*norm, v2.y*norm, v2.z*norm, v2.w*norm));
    red_v4(dst + 12, make_float4(v3.x*norm, v3.y*norm, v3.z*norm, v3.w*norm));
}

// ---------------------------------------------------------------------------
// 4. r1 = relu(agg1 + b1); agg2 self-loop init = r1 * dinv^2
// ---------------------------------------------------------------------------
__global__ void k_relu_init2(const float* __restrict__ b1) {
    int i = blockIdx.x * blockDim.x + threadIdx.x;
    if (i >= N_NODES * F_HID) return;
    int node = i >> 4;
    int f = i & 15;
    float v = fmaxf(g_agg1[i] + b1[f], 0.0f);
    g_r1[i] = v;
    float di = g_dinv[node];
    g_agg2[i] = v * (di * di);
}

// ---------------------------------------------------------------------------
// 5. out = log_softmax(agg2 @ W2 + b2)
// ---------------------------------------------------------------------------
__global__ void k_final(const float* __restrict__ W2,
                        const float* __restrict__ b2,
                        float* __restrict__ out) {
    __shared__ float sW[F_HID * F_OUT];
    __shared__ float sb[F_OUT];
    for (int i = threadIdx.x; i < F_HID * F_OUT; i += blockDim.x) sW[i] = W2[i];
    for (int i = threadIdx.x; i < F_OUT; i += blockDim.x) sb[i] = b2[i];
    __syncthreads();

    int node = blockIdx.x * blockDim.x + threadIdx.x;
    if (node >= N_NODES) return;

    float a[F_HID];
    const float4* ar = reinterpret_cast<const float4*>(g_agg2 + (size_t)node * F_HID);
#pragma unroll
    for (int q = 0; q < F_HID / 4; q++) {
        float4 v = ar[q];
        a[q*4+0] = v.x; a[q*4+1] = v.y; a[q*4+2] = v.z; a[q*4+3] = v.w;
    }

    float z[F_OUT];
#pragma unroll
    for (int c = 0; c < F_OUT; c++) {
        float s = sb[c];
#pragma unroll
        for (int k = 0; k < F_HID; k++)
            s = fmaf(a[k], sW[k * F_OUT + c], s);
        z[c] = s;
    }

    float m = z[0];
#pragma unroll
    for (int c = 1; c < F_OUT; c++) m = fmaxf(m, z[c]);
    float s = 0.0f;
#pragma unroll
    for (int c = 0; c < F_OUT; c++) s += expf(z[c] - m);
    float lse = m + logf(s);

    float* o = out + (size_t)node * F_OUT;
#pragma unroll
    for (int c = 0; c < F_OUT; c++) o[c] = z[c] - lse;
}

// ---------------------------------------------------------------------------
// launch
// ---------------------------------------------------------------------------
extern "C" void kernel_launch(void* const* d_in, const int* in_sizes, int n_in,
                              void* d_out, int out_size) {
    const float* x  = nullptr;
    const void*  ei = nullptr;
    const float* ew = nullptr;
    const float* W1 = nullptr;
    const float* b1 = nullptr;
    const float* W2 = nullptr;
    const float* b2 = nullptr;

    for (int i = 0; i < n_in; i++) {
        switch (in_sizes[i]) {
            case N_NODES * F_IN:   x  = (const float*)d_in[i]; break;
            case 2 * E_EDGES:      ei = d_in[i];               break;
            case E_EDGES:          ew = (const float*)d_in[i]; break;
            case F_IN * F_HID:     W1 = (const float*)d_in[i]; break;
            case F_HID:            b1 = (const float*)d_in[i]; break;
            case F_HID * F_OUT:    W2 = (const float*)d_in[i]; break;
            case F_OUT:            b2 = (const float*)d_in[i]; break;
            default: break;
        }
    }
    float* out = (float*)d_out;

    const int T  = 256;
    const int GE = (E_EDGES + T - 1) / T;
    const int GN = (N_NODES + T - 1) / T;

    k_detect<<<1, 32>>>((const long long*)ei);

    // degree + norm precompute
    k_deg_init<<<GN, T>>>();
    k_copy_w<<<GE, T>>>(ew);
    k_edges<<<GE, T>>>(ei, ew);
    k_dinv<<<GN, T>>>();
    k_prep<<<GE, T>>>();

    // layer 1
    k_gemm1<<<(N_NODES + 127) / 128, 128>>>(x, W1);
    k_scatter<0><<<GE, T>>>();

    // relu + layer 2
    k_relu_init2<<<(N_NODES * F_HID + T - 1) / T, T>>>(b1);
    k_scatter<1><<<GE, T>>>();

    // out-projection + log_softmax
    k_final<<<(N_NODES + 127) / 128, 128>>>(W2, b2, out);
}

// round 6
// speedup vs baseline: 1.7759x; 1.2304x over previous
#include <cuda_runtime.h>
#include <cuda_bf16.h>
#include <math.h>

#define N_NODES 100000
#define E_EDGES 3200000
#define F_IN    256
#define F_HID   16
#define F_OUT   40

#define SCAN_BS 1024
#define SCAN_NB ((N_NODES + SCAN_BS - 1) / SCAN_BS)   // 98

// -------- scratch (static device globals; 16B-aligned) ----------------------
__device__ __align__(16) float g_deg   [N_NODES];
__device__ __align__(16) float g_dinv  [N_NODES];
__device__ __align__(16) float g_h1    [N_NODES * F_HID];
__device__ __align__(16) float g_agg1  [N_NODES * F_HID];
__device__ __align__(16) float g_agg2  [N_NODES * F_HID];
__device__ __align__(16) int   g_row   [E_EDGES];
__device__ __align__(16) int   g_col   [E_EDGES];
__device__ __align__(16) int   g_cnt   [N_NODES];
__device__ __align__(16) int   g_ptr   [N_NODES + 1];
__device__ __align__(16) int   g_cursor[N_NODES];
__device__ __align__(16) int2  g_sedge [E_EDGES];      // {row, __float_as_int(norm)}
__device__ __align__(16) int   g_bsum  [SCAN_NB];
__device__ __align__(16) int   g_boff  [SCAN_NB];
__device__ int g_idx32;   // 1 => edge_index is int32, 0 => int64

__device__ __forceinline__ int load_idx(const void* __restrict__ ei, long long p) {
    if (g_idx32) return ((const int*)ei)[p];
    return (int)(((const long long*)ei)[p]);
}

// ---------------------------------------------------------------------------
// 0. detect edge_index dtype (parallel; int64 in-range values => idx64)
// ---------------------------------------------------------------------------
__global__ void k_detect(const long long* __restrict__ ei) {
    __shared__ int s_bad;
    if (threadIdx.x == 0) s_bad = 0;
    __syncthreads();
    int bad = 0;
#pragma unroll
    for (int q = 0; q < 8; q++) {
        long long v = ei[threadIdx.x + q * 512];
        if (v < 0 || v >= N_NODES) bad = 1;
    }
    if (bad) atomicOr(&s_bad, 1);
    __syncthreads();
    if (threadIdx.x == 0) g_idx32 = s_bad;
}

// ---------------------------------------------------------------------------
// 1. node init, edge decode + degree/count histogram, dinv
// ---------------------------------------------------------------------------
__global__ void k_init_nodes() {
    int i = blockIdx.x * blockDim.x + threadIdx.x;
    if (i < N_NODES) { g_deg[i] = 1.0f; g_cnt[i] = 0; }
}

__global__ void k_edges(const void* __restrict__ ei,
                        const float* __restrict__ ew) {
    int e = blockIdx.x * blockDim.x + threadIdx.x;
    if (e >= E_EDGES) return;
    int row = load_idx(ei, e);
    int col = load_idx(ei, (long long)E_EDGES + e);
    if ((unsigned)row >= (unsigned)N_NODES) row = 0;
    if ((unsigned)col >= (unsigned)N_NODES) col = 0;
    g_row[e] = row;
    g_col[e] = col;
    atomicAdd(&g_deg[col], ew[e]);
    atomicAdd(&g_cnt[col], 1);
}

__global__ void k_dinv() {
    int i = blockIdx.x * blockDim.x + threadIdx.x;
    if (i < N_NODES) {
        float d = g_deg[i];
        g_dinv[i] = (d > 0.0f) ? rsqrtf(d) : 0.0f;
    }
}

// ---------------------------------------------------------------------------
// 2. exclusive scan of g_cnt -> g_ptr  (block scan + block-sum scan + add)
// ---------------------------------------------------------------------------
__global__ void k_scan_block() {
    __shared__ int s[SCAN_BS];
    int i = blockIdx.x * SCAN_BS + threadIdx.x;
    int v = (i < N_NODES) ? g_cnt[i] : 0;
    s[threadIdx.x] = v;
    __syncthreads();
#pragma unroll
    for (int off = 1; off < SCAN_BS; off <<= 1) {
        int t = (threadIdx.x >= off) ? s[threadIdx.x - off] : 0;
        __syncthreads();
        s[threadIdx.x] += t;
        __syncthreads();
    }
    if (i < N_NODES) g_ptr[i] = s[threadIdx.x] - v;   // exclusive within block
    if (threadIdx.x == SCAN_BS - 1) g_bsum[blockIdx.x] = s[SCAN_BS - 1];
}

__global__ void k_scan_bsum() {
    if (threadIdx.x == 0) {
        int run = 0;
        for (int b = 0; b < SCAN_NB; b++) {
            g_boff[b] = run;
            run += g_bsum[b];
        }
    }
}

__global__ void k_scan_add() {
    int i = blockIdx.x * blockDim.x + threadIdx.x;
    if (i < N_NODES) {
        int p = g_ptr[i] + g_boff[i / SCAN_BS];
        g_ptr[i] = p;
        g_cursor[i] = p;
    }
    if (i == 0) g_ptr[N_NODES] = E_EDGES;
}

// ---------------------------------------------------------------------------
// 3. fill CSR: packed (row, norm) sorted by col
// ---------------------------------------------------------------------------
__global__ void k_fill(const float* __restrict__ ew) {
    int e = blockIdx.x * blockDim.x + threadIdx.x;
    if (e >= E_EDGES) return;
    int row = g_row[e];
    int col = g_col[e];
    float norm = g_dinv[row] * ew[e] * g_dinv[col];
    int pos = atomicAdd(&g_cursor[col], 1);
    g_sedge[pos] = make_int2(row, __float_as_int(norm));
}

// ---------------------------------------------------------------------------
// 4. h1 = x @ W1 (thread-per-node, W1 in smem)
// ---------------------------------------------------------------------------
__global__ void k_gemm1(const float* __restrict__ x,
                        const float* __restrict__ W1) {
    __shared__ float sW[F_IN * F_HID];   // 16 KB
    for (int i = threadIdx.x; i < F_IN * F_HID; i += blockDim.x)
        sW[i] = W1[i];
    __syncthreads();

    int node = blockIdx.x * blockDim.x + threadIdx.x;
    if (node >= N_NODES) return;

    float acc[F_HID];
#pragma unroll
    for (int f = 0; f < F_HID; f++) acc[f] = 0.0f;

    const float4* xr = reinterpret_cast<const float4*>(x + (size_t)node * F_IN);
#pragma unroll 4
    for (int k4 = 0; k4 < F_IN / 4; k4++) {
        float4 xv = xr[k4];
        int kb = k4 * 4;
#pragma unroll
        for (int f = 0; f < F_HID; f++) {
            acc[f] = fmaf(xv.x, sW[(kb + 0) * F_HID + f], acc[f]);
            acc[f] = fmaf(xv.y, sW[(kb + 1) * F_HID + f], acc[f]);
            acc[f] = fmaf(xv.z, sW[(kb + 2) * F_HID + f], acc[f]);
            acc[f] = fmaf(xv.w, sW[(kb + 3) * F_HID + f], acc[f]);
        }
    }

    float4* h1o = reinterpret_cast<float4*>(g_h1 + (size_t)node * F_HID);
#pragma unroll
    for (int q = 0; q < F_HID / 4; q++)
        h1o[q] = make_float4(acc[q*4+0], acc[q*4+1], acc[q*4+2], acc[q*4+3]);
}

// ---------------------------------------------------------------------------
// 5. pull-gather aggregation: half-warp (16 lanes = 16 features) per node.
//    LAYER 0: agg1[n] = h1[n]*dinv^2          + sum h1[row]*norm
//    LAYER 1: agg2[n] = relu(agg1[n]+b1)*dinv^2 + sum relu(agg1[row]+b1)*norm
// ---------------------------------------------------------------------------
template <int LAYER>
__global__ void k_gather(const float* __restrict__ b1) {
    int node = blockIdx.x * 16 + (threadIdx.x >> 4);
    int f    = threadIdx.x & 15;
    if (node >= N_NODES) return;

    const float* src = (LAYER == 0) ? g_h1 : g_agg1;
    float bf = (LAYER == 0) ? 0.0f : b1[f];

    float di  = g_dinv[node];
    float self = src[(size_t)node * F_HID + f];
    if (LAYER == 1) self = fmaxf(self + bf, 0.0f);
    float acc = self * di * di;

    int start = g_ptr[node];
    int end   = g_ptr[node + 1];
#pragma unroll 4
    for (int i = start; i < end; i++) {
        int2 e = g_sedge[i];                 // broadcast across 16 lanes
        float v = src[(size_t)e.x * F_HID + f];
        if (LAYER == 1) v = fmaxf(v + bf, 0.0f);
        acc = fmaf(v, __int_as_float(e.y), acc);
    }

    float* dst = (LAYER == 0) ? g_agg1 : g_agg2;
    dst[(size_t)node * F_HID + f] = acc;
}

// ---------------------------------------------------------------------------
// 6. out = log_softmax(agg2 @ W2 + b2)
// ---------------------------------------------------------------------------
__global__ void k_final(const float* __restrict__ W2,
                        const float* __restrict__ b2,
                        float* __restrict__ out) {
    __shared__ float sW[F_HID * F_OUT];
    __shared__ float sb[F_OUT];
    for (int i = threadIdx.x; i < F_HID * F_OUT; i += blockDim.x) sW[i] = W2[i];
    for (int i = threadIdx.x; i < F_OUT; i += blockDim.x) sb[i] = b2[i];
    __syncthreads();

    int node = blockIdx.x * blockDim.x + threadIdx.x;
    if (node >= N_NODES) return;

    float a[F_HID];
    const float4* ar = reinterpret_cast<const float4*>(g_agg2 + (size_t)node * F_HID);
#pragma unroll
    for (int q = 0; q < F_HID / 4; q++) {
        float4 v = ar[q];
        a[q*4+0] = v.x; a[q*4+1] = v.y; a[q*4+2] = v.z; a[q*4+3] = v.w;
    }

    float z[F_OUT];
#pragma unroll
    for (int c = 0; c < F_OUT; c++) {
        float s = sb[c];
#pragma unroll
        for (int k = 0; k < F_HID; k++)
            s = fmaf(a[k], sW[k * F_OUT + c], s);
        z[c] = s;
    }

    float m = z[0];
#pragma unroll
    for (int c = 1; c < F_OUT; c++) m = fmaxf(m, z[c]);
    float s = 0.0f;
#pragma unroll
    for (int c = 0; c < F_OUT; c++) s += expf(z[c] - m);
    float lse = m + logf(s);

    float* o = out + (size_t)node * F_OUT;
#pragma unroll
    for (int c = 0; c < F_OUT; c++) o[c] = z[c] - lse;
}

// ---------------------------------------------------------------------------
// launch
// ---------------------------------------------------------------------------
extern "C" void kernel_launch(void* const* d_in, const int* in_sizes, int n_in,
                              void* d_out, int out_size) {
    const float* x  = nullptr;
    const void*  ei = nullptr;
    const float* ew = nullptr;
    const float* W1 = nullptr;
    const float* b1 = nullptr;
    const float* W2 = nullptr;
    const float* b2 = nullptr;

    for (int i = 0; i < n_in; i++) {
        switch (in_sizes[i]) {
            case N_NODES * F_IN:   x  = (const float*)d_in[i]; break;
            case 2 * E_EDGES:      ei = d_in[i];               break;
            case E_EDGES:          ew = (const float*)d_in[i]; break;
            case F_IN * F_HID:     W1 = (const float*)d_in[i]; break;
            case F_HID:            b1 = (const float*)d_in[i]; break;
            case F_HID * F_OUT:    W2 = (const float*)d_in[i]; break;
            case F_OUT:            b2 = (const float*)d_in[i]; break;
            default: break;
        }
    }
    float* out = (float*)d_out;

    const int T  = 256;
    const int GE = (E_EDGES + T - 1) / T;
    const int GN = (N_NODES + T - 1) / T;

    k_detect<<<1, 512>>>((const long long*)ei);

    // graph preprocessing: degree, CSR
    k_init_nodes<<<GN, T>>>();
    k_edges<<<GE, T>>>(ei, ew);
    k_dinv<<<GN, T>>>();
    k_scan_block<<<SCAN_NB, SCAN_BS>>>();
    k_scan_bsum<<<1, 32>>>();
    k_scan_add<<<GN, T>>>();
    k_fill<<<GE, T>>>(ew);

    // layer 1
    k_gemm1<<<(N_NODES + 127) / 128, 128>>>(x, W1);
    k_gather<0><<<(N_NODES + 15) / 16, 256>>>(b1);

    // layer 2 (relu fused into gather)
    k_gather<1><<<(N_NODES + 15) / 16, 256>>>(b1);

    // out-projection + log_softmax
    k_final<<<(N_NODES + 127) / 128, 128>>>(W2, b2, out);
}